// round 2
// baseline (speedup 1.0000x reference)
#include <cuda_runtime.h>
#include <cuda_fp16.h>
#include <cstdint>

#define NROWS  128
#define NCOLS  524288
#define NANG   8128
#define TILE_N 128
#define NTILES (NCOLS / TILE_N)   // 4096

// ============================================================================
// Device globals (no cudaMalloc allowed): R split into fp16 hi/lo
// ============================================================================
__device__ __half g_Rhi[NROWS * NROWS];
__device__ __half g_Rlo[NROWS * NROWS];

// ============================================================================
// Kernel 1: build rotation matrix R via sequential Givens chain.
// One CTA, 128 threads; thread j owns column j of R (columns independent).
// ============================================================================
#define SMEM1 (NROWS * NROWS * 4 + NANG * 8)   // R (64KB) + float2 cs (63.5KB)

__global__ void __launch_bounds__(128, 1)
build_R_kernel(const float* __restrict__ angles)
{
    extern __shared__ float sm1[];
    float*  Rs = sm1;                              // [128*128]
    float2* cs = (float2*)(sm1 + NROWS * NROWS);   // [NANG] (c, s)

    const int j = threadIdx.x;

    for (int k = j; k < NANG; k += 128) {
        float s, c;
        sincosf(angles[k], &s, &c);
        cs[k] = make_float2(c, s);
    }
    for (int r = 0; r < NROWS; r++)
        Rs[r * NROWS + j] = (r == j) ? 1.0f : 0.0f;
    __syncthreads();

    int k = 0;
    for (int p = 0; p < NROWS - 1; p++) {
        float rp = Rs[p * NROWS + j];
        #pragma unroll 4
        for (int q = p + 1; q < NROWS; q++, k++) {
            float2 a = cs[k];
            float rq = Rs[q * NROWS + j];
            Rs[q * NROWS + j] = a.y * rp + a.x * rq;   // s*rp + c*rq
            rp = a.x * rp - a.y * rq;                  // c*rp - s*rq
        }
        Rs[p * NROWS + j] = rp;
    }

    // fp16 hi/lo split (column j only -> no sync needed)
    for (int r = 0; r < NROWS; r++) {
        float v = Rs[r * NROWS + j];
        __half h = __float2half_rn(v);
        __half l = __float2half_rn(v - __half2float(h));
        g_Rhi[r * NROWS + j] = h;
        g_Rlo[r * NROWS + j] = l;
    }
}

// ============================================================================
// Kernel 2: out = diag(mus) * (R @ X) via mma.sync m16n8k16 fp16, 3-term split
//   D = Rhi*Xhi + Rlo*Xhi + Rhi*Xlo   (fp32 accumulate)
//   A = R fragments resident in registers. B = X tile staged via cp.async
//   (raw fp32, double buffered), split to fp16 hi/lo in SMEM, consumed with
//   ldmatrix.x4.trans. Epilogue: scale by mus, direct STG.64.
// ============================================================================

#define RAW_PITCH 512            // fp32 row bytes (128 floats)
#define PITCH_B   272            // fp16 tile row bytes: 128*2 + 16 pad (17x16B)
#define OFF_RAW0  0
#define OFF_RAW1  65536
#define OFF_BHI   131072
#define OFF_BLO   (131072 + 34816)
#define SMEM2     (131072 + 2 * 34816)   // 200704 bytes

__device__ __forceinline__ uint32_t smem_u32(const void* p) {
    uint32_t a;
    asm("{ .reg .u64 t; cvta.to.shared.u64 t, %1; cvt.u32.u64 %0, t; }"
        : "=r"(a) : "l"(p));
    return a;
}

__device__ __forceinline__ void cp_async16(uint32_t dst, const void* src) {
    asm volatile("cp.async.cg.shared.global [%0], [%1], 16;"
                 :: "r"(dst), "l"(src) : "memory");
}
#define CP_COMMIT()  asm volatile("cp.async.commit_group;" ::: "memory")
#define CP_WAIT(N)   asm volatile("cp.async.wait_group %0;" :: "n"(N) : "memory")

__device__ __forceinline__ void ldsm4t(uint32_t& r0, uint32_t& r1,
                                       uint32_t& r2, uint32_t& r3, uint32_t addr)
{
    asm volatile("ldmatrix.sync.aligned.m8n8.x4.trans.shared.b16 "
                 "{%0,%1,%2,%3}, [%4];"
                 : "=r"(r0), "=r"(r1), "=r"(r2), "=r"(r3) : "r"(addr));
}

__device__ __forceinline__ void mma16816(float* d, const uint32_t* a,
                                         uint32_t b0, uint32_t b1)
{
    asm volatile("mma.sync.aligned.m16n8k16.row.col.f32.f16.f16.f32 "
                 "{%0,%1,%2,%3}, {%4,%5,%6,%7}, {%8,%9}, {%0,%1,%2,%3};"
                 : "+f"(d[0]), "+f"(d[1]), "+f"(d[2]), "+f"(d[3])
                 : "r"(a[0]), "r"(a[1]), "r"(a[2]), "r"(a[3]),
                   "r"(b0), "r"(b1));
}

__device__ __forceinline__ void issue_tile_load(const float* __restrict__ X,
                                                int t, uint32_t raw_s, int tid)
{
    const size_t c0 = (size_t)t * TILE_N;
    #pragma unroll
    for (int j = 0; j < 16; j++) {
        int c  = tid + j * 256;        // 0..4095 16B-chunk index
        int k  = c >> 5;               // row 0..127
        int ch = c & 31;               // 16B chunk within row
        cp_async16(raw_s + k * RAW_PITCH + ch * 16,
                   X + (size_t)k * NCOLS + c0 + ch * 4);
    }
    CP_COMMIT();
}

__global__ void __launch_bounds__(256, 1)
gemm_kernel(const float* __restrict__ X, const float* __restrict__ mus,
            float* __restrict__ out)
{
    extern __shared__ char smem[];
    const uint32_t sbase = smem_u32(smem);
    const int tid  = threadIdx.x;
    const int w    = tid >> 5;
    const int lane = tid & 31;

    // ---- A fragments (R hi/lo) resident in registers: warp owns rows [16w,16w+16)
    const int r0 = w * 16 + (lane >> 2);
    const int kc = (lane & 3) * 2;
    uint32_t ahi[8][4], alo[8][4];
    #pragma unroll
    for (int ks = 0; ks < 8; ks++) {
        int kb = ks * 16 + kc;
        ahi[ks][0] = *(const uint32_t*)&g_Rhi[(r0    ) * 128 + kb    ];
        ahi[ks][1] = *(const uint32_t*)&g_Rhi[(r0 + 8) * 128 + kb    ];
        ahi[ks][2] = *(const uint32_t*)&g_Rhi[(r0    ) * 128 + kb + 8];
        ahi[ks][3] = *(const uint32_t*)&g_Rhi[(r0 + 8) * 128 + kb + 8];
        alo[ks][0] = *(const uint32_t*)&g_Rlo[(r0    ) * 128 + kb    ];
        alo[ks][1] = *(const uint32_t*)&g_Rlo[(r0 + 8) * 128 + kb    ];
        alo[ks][2] = *(const uint32_t*)&g_Rlo[(r0    ) * 128 + kb + 8];
        alo[ks][3] = *(const uint32_t*)&g_Rlo[(r0 + 8) * 128 + kb + 8];
    }
    const float s0 = mus[r0];
    const float s1 = mus[r0 + 8];

    // ldmatrix per-lane byte offset inside a (k16 x n16) block
    const uint32_t loff = (uint32_t)((lane & 7) + ((lane >> 3) & 1) * 8) * PITCH_B
                        + (uint32_t)((lane >> 4) & 1) * 16;
    const uint32_t bhi_s = sbase + OFF_BHI;
    const uint32_t blo_s = sbase + OFF_BLO;

    const int stride = gridDim.x;
    int t = blockIdx.x;
    if (t >= NTILES) return;

    int bp = 0;
    issue_tile_load(X, t, sbase + OFF_RAW0, tid);

    for (; t < NTILES; t += stride) {
        const int tn = t + stride;
        if (tn < NTILES) {
            issue_tile_load(X, tn, sbase + (bp ? OFF_RAW0 : OFF_RAW1), tid);
            CP_WAIT(1);
        } else {
            CP_WAIT(0);
        }
        __syncthreads();   // raw[bp] visible; previous tile's MMA reads done

        // ---- convert raw fp32 -> fp16 hi/lo tiles ----
        {
            const float* raw = (const float*)(smem + (bp ? OFF_RAW1 : OFF_RAW0));
            #pragma unroll
            for (int i = 0; i < 32; i++) {
                int e  = tid + i * 256;      // 0..8191 pair index
                int k  = e >> 6;             // row
                int np = e & 63;             // pair of columns
                float2 x = *(const float2*)(raw + k * 128 + np * 2);
                __half h0 = __float2half_rn(x.x);
                __half h1 = __float2half_rn(x.y);
                __half l0 = __float2half_rn(x.x - __half2float(h0));
                __half l1 = __float2half_rn(x.y - __half2float(h1));
                uint32_t hw = (uint32_t)__half_as_ushort(h0)
                            | ((uint32_t)__half_as_ushort(h1) << 16);
                uint32_t lw = (uint32_t)__half_as_ushort(l0)
                            | ((uint32_t)__half_as_ushort(l1) << 16);
                *(uint32_t*)(smem + OFF_BHI + k * PITCH_B + np * 4) = hw;
                *(uint32_t*)(smem + OFF_BLO + k * PITCH_B + np * 4) = lw;
            }
        }
        __syncthreads();   // B tiles visible

        // ---- MMA: acc = Rhi*Xhi + Rlo*Xhi + Rhi*Xlo ----
        float acc[16][4];
        #pragma unroll
        for (int i = 0; i < 16; i++)
            #pragma unroll
            for (int q = 0; q < 4; q++) acc[i][q] = 0.0f;

        for (int ks = 0; ks < 8; ks++) {
            const uint32_t rowo = (uint32_t)(ks * 16) * PITCH_B + loff;
            #pragma unroll
            for (int nb = 0; nb < 8; nb++) {
                uint32_t h0, h1, h2, h3, l0, l1, l2, l3;
                ldsm4t(h0, h1, h2, h3, bhi_s + rowo + nb * 32);
                ldsm4t(l0, l1, l2, l3, blo_s + rowo + nb * 32);
                mma16816(acc[2 * nb    ], ahi[ks], h0, h1);
                mma16816(acc[2 * nb + 1], ahi[ks], h2, h3);
                mma16816(acc[2 * nb    ], alo[ks], h0, h1);
                mma16816(acc[2 * nb + 1], alo[ks], h2, h3);
                mma16816(acc[2 * nb    ], ahi[ks], l0, l1);
                mma16816(acc[2 * nb + 1], ahi[ks], l2, l3);
            }
        }

        // ---- epilogue: scale by mus, direct stores ----
        {
            const size_t c0 = (size_t)t * TILE_N + kc;
            float* o0 = out + (size_t)(r0    ) * NCOLS + c0;
            float* o1 = out + (size_t)(r0 + 8) * NCOLS + c0;
            #pragma unroll
            for (int nb = 0; nb < 16; nb++) {
                float2 v0 = make_float2(s0 * acc[nb][0], s0 * acc[nb][1]);
                float2 v1 = make_float2(s1 * acc[nb][2], s1 * acc[nb][3]);
                *(float2*)(o0 + nb * 8) = v0;
                *(float2*)(o1 + nb * 8) = v1;
            }
        }
        __syncthreads();   // B consumption done before next convert overwrites
        bp ^= 1;
    }
}

// ============================================================================
// Launch
// ============================================================================
extern "C" void kernel_launch(void* const* d_in, const int* in_sizes, int n_in,
                              void* d_out, int out_size)
{
    const float* X      = (const float*)d_in[0];
    const float* angles = (const float*)d_in[1];
    const float* mus    = (const float*)d_in[2];
    float* out          = (float*)d_out;

    cudaFuncSetAttribute(build_R_kernel,
                         cudaFuncAttributeMaxDynamicSharedMemorySize, SMEM1);
    cudaFuncSetAttribute(gemm_kernel,
                         cudaFuncAttributeMaxDynamicSharedMemorySize, SMEM2);

    int sm_count = 148;
    cudaDeviceGetAttribute(&sm_count, cudaDevAttrMultiProcessorCount, 0);
    int grid = sm_count;
    if (grid > NTILES) grid = NTILES;

    build_R_kernel<<<1, 128, SMEM1>>>(angles);
    gemm_kernel<<<grid, 256, SMEM2>>>(X, mus, out);
}

// round 3
// speedup vs baseline: 1.9246x; 1.9246x over previous
#include <cuda_runtime.h>
#include <cuda_fp16.h>
#include <cstdint>

#define NROWS  128
#define NCOLS  524288
#define NANG   8128
#define TILE_N 128
#define NTILES (NCOLS / TILE_N)   // 4096

#define NSEG   16
#define SEGLEN (NANG / NSEG)      // 508

// ============================================================================
// Device globals (no cudaMalloc allowed)
// ============================================================================
__device__ __half g_Rhi[NROWS * NROWS];
__device__ __half g_Rlo[NROWS * NROWS];
__device__ float  g_MA[NSEG][NROWS * NROWS];   // segment / ping buffers
__device__ float  g_MB[8][NROWS * NROWS];      // pong buffers

// ============================================================================
// Kernel 1: build 16 partial rotation products in parallel.
// CTA s applies rotations k in [s*508, (s+1)*508) to identity -> g_MA[s].
// Thread j owns column j (columns independent -> no syncs in the chain).
// ============================================================================
#define SMEM_SEG (NROWS * NROWS * 4 + SEGLEN * 8)   // 64KB + ~4KB

__global__ void __launch_bounds__(128, 1)
build_seg_kernel(const float* __restrict__ angles)
{
    extern __shared__ float sm1[];
    float*  Rs = sm1;                              // [128*128]
    float2* cs = (float2*)(sm1 + NROWS * NROWS);   // [SEGLEN]

    const int s  = blockIdx.x;
    const int lo = s * SEGLEN;
    const int j  = threadIdx.x;

    for (int k = j; k < SEGLEN; k += 128) {
        float sn, c;
        sincosf(angles[lo + k], &sn, &c);
        cs[k] = make_float2(c, sn);
    }
    for (int r = 0; r < NROWS; r++)
        Rs[r * NROWS + j] = (r == j) ? 1.0f : 0.0f;
    __syncthreads();

    // locate starting (p,q) for global index lo in triu(N,1) order
    int p = 0, cum = 0;
    while (cum + (127 - p) <= lo) { cum += 127 - p; p++; }
    int q = p + 1 + (lo - cum);

    float rp = Rs[p * NROWS + j];
    for (int kk = 0; kk < SEGLEN; kk++) {
        float2 a = cs[kk];
        float rq = Rs[q * NROWS + j];
        Rs[q * NROWS + j] = fmaf(a.y, rp, a.x * rq);   // s*rp + c*rq
        rp = fmaf(a.x, rp, -a.y * rq);                 // c*rp - s*rq
        if (++q == NROWS) {
            Rs[p * NROWS + j] = rp;
            p++;
            if (p < NROWS - 1) { q = p + 1; rp = Rs[p * NROWS + j]; }
        }
    }
    if (p < NROWS - 1) Rs[p * NROWS + j] = rp;
    __syncthreads();

    float* dst = g_MA[s];
    for (int r = 0; r < NROWS; r++)
        dst[r * NROWS + j] = Rs[r * NROWS + j];
}

// ============================================================================
// Kernel 2: pairwise combine round.  C_i = src[2i+1] @ src[2i] (128x128 fp32).
// grid = nprod*4 CTAs (4 col-blocks of 32 per product), 256 threads.
// final!=0: write fp16 hi/lo split to g_Rhi/g_Rlo instead of dst buffer.
// ============================================================================
#define SMEM_CMB (NROWS * NROWS * 4 + NROWS * 32 * 4)   // 64KB + 16KB

__global__ void __launch_bounds__(256, 1)
combine_kernel(int src_sel, int dst_sel, int final_round)
{
    extern __shared__ float smc[];
    float* As = smc;                 // [128][128]
    float* Bs = smc + NROWS * NROWS; // [128][32]

    const int prod = blockIdx.x >> 2;
    const int cb   = blockIdx.x & 3;
    const int tid  = threadIdx.x;

    const float* srcbase = src_sel ? &g_MB[0][0] : &g_MA[0][0];
    const float* A = srcbase + (size_t)(2 * prod + 1) * NROWS * NROWS;
    const float* B = srcbase + (size_t)(2 * prod) * NROWS * NROWS;

    for (int i = tid; i < NROWS * NROWS; i += 256) As[i] = A[i];
    for (int i = tid; i < NROWS * 32; i += 256) {
        int k = i >> 5, jl = i & 31;
        Bs[k * 32 + jl] = B[k * NROWS + cb * 32 + jl];
    }
    __syncthreads();

    const int jl = tid & 31;
    const int r0 = (tid >> 5) * 16;

    float acc[16];
    #pragma unroll
    for (int i = 0; i < 16; i++) acc[i] = 0.0f;

    for (int k = 0; k < NROWS; k++) {
        float b = Bs[k * 32 + jl];
        #pragma unroll
        for (int i = 0; i < 16; i++)
            acc[i] = fmaf(As[(r0 + i) * NROWS + k], b, acc[i]);
    }

    if (final_round) {
        #pragma unroll
        for (int i = 0; i < 16; i++) {
            float v = acc[i];
            __half h = __float2half_rn(v);
            __half l = __float2half_rn(v - __half2float(h));
            int o = (r0 + i) * NROWS + cb * 32 + jl;
            g_Rhi[o] = h;
            g_Rlo[o] = l;
        }
    } else {
        float* dstbase = dst_sel ? &g_MB[0][0] : &g_MA[0][0];
        float* C = dstbase + (size_t)prod * NROWS * NROWS;
        #pragma unroll
        for (int i = 0; i < 16; i++)
            C[(r0 + i) * NROWS + cb * 32 + jl] = acc[i];
    }
}

// ============================================================================
// Kernel 3: out = diag(mus) * (R @ X) via mma.sync m16n8k16 fp16, 2-term split
//   D = Rhi*Xhi + Rlo*Xhi   (R exact to fp16-pair; only X rounding remains)
//   A = R fragments resident in registers. B = Xhi tile in SMEM (cp.async raw
//   fp32 stage -> in-smem convert), ldmatrix.x4.trans.  2 CTAs per SM.
// ============================================================================
#define RAW_PITCH 512            // fp32 row bytes (128 floats)
#define PITCH_B   272            // fp16 row bytes: 256 + 16 pad
#define OFF_RAW   0
#define OFF_BHI   65536
#define SMEM2     (65536 + 34816)   // 100352 -> 2 CTAs/SM

__device__ __forceinline__ uint32_t smem_u32(const void* p) {
    uint32_t a;
    asm("{ .reg .u64 t; cvta.to.shared.u64 t, %1; cvt.u32.u64 %0, t; }"
        : "=r"(a) : "l"(p));
    return a;
}
__device__ __forceinline__ void cp_async16(uint32_t dst, const void* src) {
    asm volatile("cp.async.cg.shared.global [%0], [%1], 16;"
                 :: "r"(dst), "l"(src) : "memory");
}
#define CP_COMMIT()  asm volatile("cp.async.commit_group;" ::: "memory")
#define CP_WAIT0()   asm volatile("cp.async.wait_group 0;" ::: "memory")

__device__ __forceinline__ void ldsm4t(uint32_t& r0, uint32_t& r1,
                                       uint32_t& r2, uint32_t& r3, uint32_t addr)
{
    asm volatile("ldmatrix.sync.aligned.m8n8.x4.trans.shared.b16 "
                 "{%0,%1,%2,%3}, [%4];"
                 : "=r"(r0), "=r"(r1), "=r"(r2), "=r"(r3) : "r"(addr));
}
__device__ __forceinline__ void mma16816(float* d, const uint32_t* a,
                                         uint32_t b0, uint32_t b1)
{
    asm volatile("mma.sync.aligned.m16n8k16.row.col.f32.f16.f16.f32 "
                 "{%0,%1,%2,%3}, {%4,%5,%6,%7}, {%8,%9}, {%0,%1,%2,%3};"
                 : "+f"(d[0]), "+f"(d[1]), "+f"(d[2]), "+f"(d[3])
                 : "r"(a[0]), "r"(a[1]), "r"(a[2]), "r"(a[3]),
                   "r"(b0), "r"(b1));
}

__device__ __forceinline__ void issue_tile_load(const float* __restrict__ X,
                                                int t, uint32_t raw_s, int tid)
{
    const size_t c0 = (size_t)t * TILE_N;
    #pragma unroll
    for (int j = 0; j < 16; j++) {
        int c  = tid + j * 256;        // 16B-chunk index 0..4095
        int k  = c >> 5;               // row 0..127
        int ch = c & 31;               // chunk within row
        cp_async16(raw_s + k * RAW_PITCH + ch * 16,
                   X + (size_t)k * NCOLS + c0 + ch * 4);
    }
    CP_COMMIT();
}

__global__ void __launch_bounds__(256, 2)
gemm_kernel(const float* __restrict__ X, const float* __restrict__ mus,
            float* __restrict__ out)
{
    extern __shared__ char smem[];
    const uint32_t sbase = smem_u32(smem);
    const int tid  = threadIdx.x;
    const int w    = tid >> 5;
    const int lane = tid & 31;

    // A fragments: warp w owns rows [16w, 16w+16)
    const int r0 = w * 16 + (lane >> 2);
    const int kc = (lane & 3) * 2;
    uint32_t ahi[8][4], alo[8][4];
    #pragma unroll
    for (int ks = 0; ks < 8; ks++) {
        int kb = ks * 16 + kc;
        ahi[ks][0] = *(const uint32_t*)&g_Rhi[(r0    ) * 128 + kb    ];
        ahi[ks][1] = *(const uint32_t*)&g_Rhi[(r0 + 8) * 128 + kb    ];
        ahi[ks][2] = *(const uint32_t*)&g_Rhi[(r0    ) * 128 + kb + 8];
        ahi[ks][3] = *(const uint32_t*)&g_Rhi[(r0 + 8) * 128 + kb + 8];
        alo[ks][0] = *(const uint32_t*)&g_Rlo[(r0    ) * 128 + kb    ];
        alo[ks][1] = *(const uint32_t*)&g_Rlo[(r0 + 8) * 128 + kb    ];
        alo[ks][2] = *(const uint32_t*)&g_Rlo[(r0    ) * 128 + kb + 8];
        alo[ks][3] = *(const uint32_t*)&g_Rlo[(r0 + 8) * 128 + kb + 8];
    }
    const float s0 = mus[r0];
    const float s1 = mus[r0 + 8];

    const uint32_t loff = (uint32_t)((lane & 7) + ((lane >> 3) & 1) * 8) * PITCH_B
                        + (uint32_t)((lane >> 4) & 1) * 16;
    const uint32_t bhi_s = sbase + OFF_BHI;
    const float*   raw   = (const float*)(smem + OFF_RAW);

    const int stride = gridDim.x;
    int t = blockIdx.x;
    if (t >= NTILES) return;

    issue_tile_load(X, t, sbase + OFF_RAW, tid);

    for (; t < NTILES; t += stride) {
        CP_WAIT0();
        __syncthreads();                 // raw tile visible to all

        // convert raw fp32 -> fp16 (hi only)
        #pragma unroll
        for (int i = 0; i < 32; i++) {
            int e  = tid + i * 256;      // pair index 0..8191
            int k  = e >> 6;
            int np = e & 63;
            float2 x = *(const float2*)(raw + k * 128 + np * 2);
            __half h0 = __float2half_rn(x.x);
            __half h1 = __float2half_rn(x.y);
            uint32_t hw = (uint32_t)__half_as_ushort(h0)
                        | ((uint32_t)__half_as_ushort(h1) << 16);
            *(uint32_t*)(smem + OFF_BHI + k * PITCH_B + np * 4) = hw;
        }
        __syncthreads();                 // Bhi ready; raw fully consumed

        int tn = t + stride;
        if (tn < NTILES)
            issue_tile_load(X, tn, sbase + OFF_RAW, tid);   // overlaps MMA

        // two column-half passes (cols 0-63, 64-127), acc regs reused
        #pragma unroll
        for (int pass = 0; pass < 2; pass++) {
            float acc[8][4];
            #pragma unroll
            for (int a = 0; a < 8; a++)
                #pragma unroll
                for (int q2 = 0; q2 < 4; q2++) acc[a][q2] = 0.0f;

            #pragma unroll
            for (int ks = 0; ks < 8; ks++) {
                const uint32_t rowo = (uint32_t)(ks * 16) * PITCH_B + loff
                                    + (uint32_t)pass * 128;
                #pragma unroll
                for (int nb = 0; nb < 4; nb++) {
                    uint32_t b0, b1, b2, b3;
                    ldsm4t(b0, b1, b2, b3, bhi_s + rowo + nb * 32);
                    mma16816(acc[2 * nb    ], ahi[ks], b0, b1);
                    mma16816(acc[2 * nb + 1], ahi[ks], b2, b3);
                    mma16816(acc[2 * nb    ], alo[ks], b0, b1);
                    mma16816(acc[2 * nb + 1], alo[ks], b2, b3);
                }
            }

            const size_t c0 = (size_t)t * TILE_N + pass * 64 + kc;
            float* o0 = out + (size_t)(r0    ) * NCOLS + c0;
            float* o1 = out + (size_t)(r0 + 8) * NCOLS + c0;
            #pragma unroll
            for (int a = 0; a < 8; a++) {
                int coff = (a >> 1) * 16 + (a & 1) * 8;
                float2 v0 = make_float2(s0 * acc[a][0], s0 * acc[a][1]);
                float2 v1 = make_float2(s1 * acc[a][2], s1 * acc[a][3]);
                *(float2*)(o0 + coff) = v0;
                *(float2*)(o1 + coff) = v1;
            }
        }
        __syncthreads();                 // Bhi consumed before next convert
    }
}

// ============================================================================
// Launch
// ============================================================================
extern "C" void kernel_launch(void* const* d_in, const int* in_sizes, int n_in,
                              void* d_out, int out_size)
{
    const float* X      = (const float*)d_in[0];
    const float* angles = (const float*)d_in[1];
    const float* mus    = (const float*)d_in[2];
    float* out          = (float*)d_out;

    cudaFuncSetAttribute(build_seg_kernel,
                         cudaFuncAttributeMaxDynamicSharedMemorySize, SMEM_SEG);
    cudaFuncSetAttribute(combine_kernel,
                         cudaFuncAttributeMaxDynamicSharedMemorySize, SMEM_CMB);
    cudaFuncSetAttribute(gemm_kernel,
                         cudaFuncAttributeMaxDynamicSharedMemorySize, SMEM2);

    int sm_count = 148;
    cudaDeviceGetAttribute(&sm_count, cudaDevAttrMultiProcessorCount, 0);
    int grid = sm_count * 2;
    if (grid > NTILES) grid = NTILES;

    // R build: 16 parallel segments, then log2 tree of 128x128 products
    build_seg_kernel<<<16, 128, SMEM_SEG>>>(angles);
    combine_kernel<<<32, 256, SMEM_CMB>>>(0, 1, 0);  // MA[16] -> MB[8]
    combine_kernel<<<16, 256, SMEM_CMB>>>(1, 0, 0);  // MB[8]  -> MA[4]
    combine_kernel<<< 8, 256, SMEM_CMB>>>(0, 1, 0);  // MA[4]  -> MB[2]
    combine_kernel<<< 4, 256, SMEM_CMB>>>(1, 0, 1);  // MB[2]  -> Rhi/Rlo

    gemm_kernel<<<grid, 256, SMEM2>>>(X, mus, out);
}

// round 4
// speedup vs baseline: 2.0959x; 1.0890x over previous
#include <cuda_runtime.h>
#include <cuda_fp16.h>
#include <cstdint>

#define NROWS  128
#define NCOLS  524288
#define NANG   8128
#define TILE_N 128
#define NTILES (NCOLS / TILE_N)   // 4096

#define NSEG   16
#define SEGLEN (NANG / NSEG)      // 508
#define MATSZ  (NROWS * NROWS)    // 16384

// ============================================================================
// Device globals (no cudaMalloc allowed). All intermediates fp16 hi/lo.
// Slots 0..15 = ping bank, 16..23 = pong bank.
// ============================================================================
__device__ __half g_Rhi[MATSZ];
__device__ __half g_Rlo[MATSZ];
__device__ __half g_Mhi[24 * MATSZ];
__device__ __half g_Mlo[24 * MATSZ];

// ============================================================================
// Common PTX helpers
// ============================================================================
__device__ __forceinline__ uint32_t smem_u32(const void* p) {
    uint32_t a;
    asm("{ .reg .u64 t; cvta.to.shared.u64 t, %1; cvt.u32.u64 %0, t; }"
        : "=r"(a) : "l"(p));
    return a;
}
__device__ __forceinline__ void cp_async16(uint32_t dst, const void* src) {
    asm volatile("cp.async.cg.shared.global [%0], [%1], 16;"
                 :: "r"(dst), "l"(src) : "memory");
}
#define CP_COMMIT()  asm volatile("cp.async.commit_group;" ::: "memory")
#define CP_WAIT0()   asm volatile("cp.async.wait_group 0;" ::: "memory")

__device__ __forceinline__ void ldsm4t(uint32_t& r0, uint32_t& r1,
                                       uint32_t& r2, uint32_t& r3, uint32_t addr)
{
    asm volatile("ldmatrix.sync.aligned.m8n8.x4.trans.shared.b16 "
                 "{%0,%1,%2,%3}, [%4];"
                 : "=r"(r0), "=r"(r1), "=r"(r2), "=r"(r3) : "r"(addr));
}
__device__ __forceinline__ void mma16816(float* d, const uint32_t* a,
                                         uint32_t b0, uint32_t b1)
{
    asm volatile("mma.sync.aligned.m16n8k16.row.col.f32.f16.f16.f32 "
                 "{%0,%1,%2,%3}, {%4,%5,%6,%7}, {%8,%9}, {%0,%1,%2,%3};"
                 : "+f"(d[0]), "+f"(d[1]), "+f"(d[2]), "+f"(d[3])
                 : "r"(a[0]), "r"(a[1]), "r"(a[2]), "r"(a[3]),
                   "r"(b0), "r"(b1));
}

#define PITCH_B   272            // fp16 tile row bytes: 256 + 16 pad

// ============================================================================
// Kernel 1: build 16 partial rotation products in parallel (fp32 in smem),
// output fp16 hi/lo into slot s. Thread j owns column j.
// ============================================================================
#define SMEM_SEG (MATSZ * 4 + SEGLEN * 8)   // 64KB + ~4KB

__global__ void __launch_bounds__(128, 1)
build_seg_kernel(const float* __restrict__ angles)
{
    extern __shared__ float sm1[];
    float*  Rs = sm1;                       // [128*128]
    float2* cs = (float2*)(sm1 + MATSZ);    // [SEGLEN]

    const int s  = blockIdx.x;
    const int lo = s * SEGLEN;
    const int j  = threadIdx.x;

    for (int k = j; k < SEGLEN; k += 128) {
        float sn, c;
        sincosf(angles[lo + k], &sn, &c);
        cs[k] = make_float2(c, sn);
    }
    for (int r = 0; r < NROWS; r++)
        Rs[r * NROWS + j] = (r == j) ? 1.0f : 0.0f;
    __syncthreads();

    // starting (p,q) for global rotation index lo in triu(N,1) order
    int p = 0, cum = 0;
    while (cum + (127 - p) <= lo) { cum += 127 - p; p++; }
    int q = p + 1 + (lo - cum);

    float rp = Rs[p * NROWS + j];
    #pragma unroll 4
    for (int kk = 0; kk < SEGLEN; kk++) {
        float2 a = cs[kk];
        float rq = Rs[q * NROWS + j];
        Rs[q * NROWS + j] = fmaf(a.y, rp, a.x * rq);
        rp = fmaf(a.x, rp, -a.y * rq);
        if (++q == NROWS) {
            Rs[p * NROWS + j] = rp;
            p++;
            if (p < NROWS - 1) { q = p + 1; rp = Rs[p * NROWS + j]; }
        }
    }
    if (p < NROWS - 1) Rs[p * NROWS + j] = rp;
    __syncthreads();

    __half* dh = g_Mhi + (size_t)s * MATSZ;
    __half* dl = g_Mlo + (size_t)s * MATSZ;
    for (int r = 0; r < NROWS; r++) {
        float v = Rs[r * NROWS + j];
        __half h = __float2half_rn(v);
        __half l = __float2half_rn(v - __half2float(h));
        dh[r * NROWS + j] = h;
        dl[r * NROWS + j] = l;
    }
}

// ============================================================================
// Kernel 2: tensor-core pairwise combine.
//   C[prod] = src[2*prod+1] @ src[2*prod], all matrices fp16 hi/lo pairs.
//   3-term: Ahi*Bhi + Alo*Bhi + Ahi*Blo, fp32 acc, re-split to hi/lo.
//   One CTA per product (256 thr, warp = 16 rows). to_R: write g_Rhi/g_Rlo.
// ============================================================================
#define SMEM_CMB (2 * 128 * PITCH_B)      // Bhi + Blo staged: 69632 B

__global__ void __launch_bounds__(256, 1)
combine_mma_kernel(int src_slot, int dst_slot, int to_R)
{
    extern __shared__ char smc[];
    const uint32_t sbase = smem_u32(smc);
    const int tid  = threadIdx.x;
    const int w    = tid >> 5;
    const int lane = tid & 31;
    const int prod = blockIdx.x;

    const __half* Ahi = g_Mhi + (size_t)(src_slot + 2 * prod + 1) * MATSZ;
    const __half* Alo = g_Mlo + (size_t)(src_slot + 2 * prod + 1) * MATSZ;
    const uint4*  Bhi_g = (const uint4*)(g_Mhi + (size_t)(src_slot + 2 * prod) * MATSZ);
    const uint4*  Blo_g = (const uint4*)(g_Mlo + (size_t)(src_slot + 2 * prod) * MATSZ);

    // stage B hi/lo into PITCH_B layout (rows of 256B -> 16 uint4 per row)
    #pragma unroll
    for (int i = tid; i < 128 * 16; i += 256) {
        int k = i >> 4, c = i & 15;
        *(uint4*)(smc + k * PITCH_B + c * 16)              = Bhi_g[i];
        *(uint4*)(smc + 128 * PITCH_B + k * PITCH_B + c * 16) = Blo_g[i];
    }

    // A fragments: warp w owns rows [16w, 16w+16)
    const int r0 = w * 16 + (lane >> 2);
    const int kc = (lane & 3) * 2;
    uint32_t ahi[8][4], alo[8][4];
    #pragma unroll
    for (int ks = 0; ks < 8; ks++) {
        int kb = ks * 16 + kc;
        ahi[ks][0] = *(const uint32_t*)&Ahi[(r0    ) * 128 + kb    ];
        ahi[ks][1] = *(const uint32_t*)&Ahi[(r0 + 8) * 128 + kb    ];
        ahi[ks][2] = *(const uint32_t*)&Ahi[(r0    ) * 128 + kb + 8];
        ahi[ks][3] = *(const uint32_t*)&Ahi[(r0 + 8) * 128 + kb + 8];
        alo[ks][0] = *(const uint32_t*)&Alo[(r0    ) * 128 + kb    ];
        alo[ks][1] = *(const uint32_t*)&Alo[(r0 + 8) * 128 + kb    ];
        alo[ks][2] = *(const uint32_t*)&Alo[(r0    ) * 128 + kb + 8];
        alo[ks][3] = *(const uint32_t*)&Alo[(r0 + 8) * 128 + kb + 8];
    }
    __syncthreads();

    const uint32_t loff = (uint32_t)((lane & 7) + ((lane >> 3) & 1) * 8) * PITCH_B
                        + (uint32_t)((lane >> 4) & 1) * 16;
    const uint32_t bhi_s = sbase;
    const uint32_t blo_s = sbase + 128 * PITCH_B;

    float acc[16][4];
    #pragma unroll
    for (int a = 0; a < 16; a++)
        #pragma unroll
        for (int q2 = 0; q2 < 4; q2++) acc[a][q2] = 0.0f;

    #pragma unroll
    for (int ks = 0; ks < 8; ks++) {
        const uint32_t rowo = (uint32_t)(ks * 16) * PITCH_B + loff;
        #pragma unroll
        for (int nb = 0; nb < 8; nb++) {
            uint32_t h0, h1, h2, h3, l0, l1, l2, l3;
            ldsm4t(h0, h1, h2, h3, bhi_s + rowo + nb * 32);
            ldsm4t(l0, l1, l2, l3, blo_s + rowo + nb * 32);
            mma16816(acc[2 * nb    ], ahi[ks], h0, h1);
            mma16816(acc[2 * nb + 1], ahi[ks], h2, h3);
            mma16816(acc[2 * nb    ], alo[ks], h0, h1);
            mma16816(acc[2 * nb + 1], alo[ks], h2, h3);
            mma16816(acc[2 * nb    ], ahi[ks], l0, l1);
            mma16816(acc[2 * nb + 1], ahi[ks], l2, l3);
        }
    }

    // epilogue: split fp32 -> fp16 hi/lo, store uint32 pairs (cols kc, kc+1)
    __half* Chi = to_R ? g_Rhi : g_Mhi + (size_t)(dst_slot + prod) * MATSZ;
    __half* Clo = to_R ? g_Rlo : g_Mlo + (size_t)(dst_slot + prod) * MATSZ;
    #pragma unroll
    for (int a = 0; a < 16; a++) {
        int col = (a >> 1) * 16 + (a & 1) * 8 + kc;
        #pragma unroll
        for (int half2i = 0; half2i < 2; half2i++) {     // row r0, r0+8
            int row = r0 + half2i * 8;
            float v0 = acc[a][2 * half2i    ];
            float v1 = acc[a][2 * half2i + 1];
            __half h0 = __float2half_rn(v0);
            __half h1 = __float2half_rn(v1);
            __half e0 = __float2half_rn(v0 - __half2float(h0));
            __half e1 = __float2half_rn(v1 - __half2float(h1));
            uint32_t hw = (uint32_t)__half_as_ushort(h0)
                        | ((uint32_t)__half_as_ushort(h1) << 16);
            uint32_t lw = (uint32_t)__half_as_ushort(e0)
                        | ((uint32_t)__half_as_ushort(e1) << 16);
            *(uint32_t*)&Chi[row * 128 + col] = hw;
            *(uint32_t*)&Clo[row * 128 + col] = lw;
        }
    }
}

// ============================================================================
// Kernel 3: out = diag(mus) * (R @ X), mma.sync fp16 2-term split, 2 CTAs/SM.
// ============================================================================
#define RAW_PITCH 512            // fp32 row bytes (128 floats)
#define OFF_RAW   0
#define OFF_BHI   65536
#define SMEM2     (65536 + 34816)   // 100352 -> 2 CTAs/SM

__device__ __forceinline__ void issue_tile_load(const float* __restrict__ X,
                                                int t, uint32_t raw_s, int tid)
{
    const size_t c0 = (size_t)t * TILE_N;
    #pragma unroll
    for (int j = 0; j < 16; j++) {
        int c  = tid + j * 256;        // 16B-chunk index 0..4095
        int k  = c >> 5;
        int ch = c & 31;
        cp_async16(raw_s + k * RAW_PITCH + ch * 16,
                   X + (size_t)k * NCOLS + c0 + ch * 4);
    }
    CP_COMMIT();
}

__global__ void __launch_bounds__(256, 2)
gemm_kernel(const float* __restrict__ X, const float* __restrict__ mus,
            float* __restrict__ out)
{
    extern __shared__ char smem[];
    const uint32_t sbase = smem_u32(smem);
    const int tid  = threadIdx.x;
    const int w    = tid >> 5;
    const int lane = tid & 31;

    const int r0 = w * 16 + (lane >> 2);
    const int kc = (lane & 3) * 2;
    uint32_t ahi[8][4], alo[8][4];
    #pragma unroll
    for (int ks = 0; ks < 8; ks++) {
        int kb = ks * 16 + kc;
        ahi[ks][0] = *(const uint32_t*)&g_Rhi[(r0    ) * 128 + kb    ];
        ahi[ks][1] = *(const uint32_t*)&g_Rhi[(r0 + 8) * 128 + kb    ];
        ahi[ks][2] = *(const uint32_t*)&g_Rhi[(r0    ) * 128 + kb + 8];
        ahi[ks][3] = *(const uint32_t*)&g_Rhi[(r0 + 8) * 128 + kb + 8];
        alo[ks][0] = *(const uint32_t*)&g_Rlo[(r0    ) * 128 + kb    ];
        alo[ks][1] = *(const uint32_t*)&g_Rlo[(r0 + 8) * 128 + kb    ];
        alo[ks][2] = *(const uint32_t*)&g_Rlo[(r0    ) * 128 + kb + 8];
        alo[ks][3] = *(const uint32_t*)&g_Rlo[(r0 + 8) * 128 + kb + 8];
    }
    const float s0 = mus[r0];
    const float s1 = mus[r0 + 8];

    const uint32_t loff = (uint32_t)((lane & 7) + ((lane >> 3) & 1) * 8) * PITCH_B
                        + (uint32_t)((lane >> 4) & 1) * 16;
    const uint32_t bhi_s = sbase + OFF_BHI;
    const float*   raw   = (const float*)(smem + OFF_RAW);

    const int stride = gridDim.x;
    int t = blockIdx.x;
    if (t >= NTILES) return;

    issue_tile_load(X, t, sbase + OFF_RAW, tid);

    for (; t < NTILES; t += stride) {
        CP_WAIT0();
        __syncthreads();                 // raw tile visible

        // convert raw fp32 -> fp16 (hi only)
        #pragma unroll
        for (int i = 0; i < 32; i++) {
            int e  = tid + i * 256;
            int k  = e >> 6;
            int np = e & 63;
            float2 x = *(const float2*)(raw + k * 128 + np * 2);
            __half h0 = __float2half_rn(x.x);
            __half h1 = __float2half_rn(x.y);
            uint32_t hw = (uint32_t)__half_as_ushort(h0)
                        | ((uint32_t)__half_as_ushort(h1) << 16);
            *(uint32_t*)(smem + OFF_BHI + k * PITCH_B + np * 4) = hw;
        }
        __syncthreads();                 // Bhi ready; raw consumed

        int tn = t + stride;
        if (tn < NTILES)
            issue_tile_load(X, tn, sbase + OFF_RAW, tid);   // overlaps MMA

        #pragma unroll
        for (int pass = 0; pass < 2; pass++) {
            float acc[8][4];
            #pragma unroll
            for (int a = 0; a < 8; a++)
                #pragma unroll
                for (int q2 = 0; q2 < 4; q2++) acc[a][q2] = 0.0f;

            #pragma unroll
            for (int ks = 0; ks < 8; ks++) {
                const uint32_t rowo = (uint32_t)(ks * 16) * PITCH_B + loff
                                    + (uint32_t)pass * 128;
                #pragma unroll
                for (int nb = 0; nb < 4; nb++) {
                    uint32_t b0, b1, b2, b3;
                    ldsm4t(b0, b1, b2, b3, bhi_s + rowo + nb * 32);
                    mma16816(acc[2 * nb    ], ahi[ks], b0, b1);
                    mma16816(acc[2 * nb + 1], ahi[ks], b2, b3);
                    mma16816(acc[2 * nb    ], alo[ks], b0, b1);
                    mma16816(acc[2 * nb + 1], alo[ks], b2, b3);
                }
            }

            const size_t c0 = (size_t)t * TILE_N + pass * 64 + kc;
            float* o0 = out + (size_t)(r0    ) * NCOLS + c0;
            float* o1 = out + (size_t)(r0 + 8) * NCOLS + c0;
            #pragma unroll
            for (int a = 0; a < 8; a++) {
                int coff = (a >> 1) * 16 + (a & 1) * 8;
                float2 v0 = make_float2(s0 * acc[a][0], s0 * acc[a][1]);
                float2 v1 = make_float2(s1 * acc[a][2], s1 * acc[a][3]);
                *(float2*)(o0 + coff) = v0;
                *(float2*)(o1 + coff) = v1;
            }
        }
        __syncthreads();                 // Bhi consumed before next convert
    }
}

// ============================================================================
// Launch
// ============================================================================
extern "C" void kernel_launch(void* const* d_in, const int* in_sizes, int n_in,
                              void* d_out, int out_size)
{
    const float* X      = (const float*)d_in[0];
    const float* angles = (const float*)d_in[1];
    const float* mus    = (const float*)d_in[2];
    float* out          = (float*)d_out;

    cudaFuncSetAttribute(build_seg_kernel,
                         cudaFuncAttributeMaxDynamicSharedMemorySize, SMEM_SEG);
    cudaFuncSetAttribute(combine_mma_kernel,
                         cudaFuncAttributeMaxDynamicSharedMemorySize, SMEM_CMB);
    cudaFuncSetAttribute(gemm_kernel,
                         cudaFuncAttributeMaxDynamicSharedMemorySize, SMEM2);

    int sm_count = 148;
    cudaDeviceGetAttribute(&sm_count, cudaDevAttrMultiProcessorCount, 0);
    int grid = sm_count * 2;
    if (grid > NTILES) grid = NTILES;

    // Build R: 16 parallel segments (slots 0..15), then tensor-core tree
    build_seg_kernel<<<16, 128, SMEM_SEG>>>(angles);
    combine_mma_kernel<<<8, 256, SMEM_CMB>>>( 0, 16, 0);  // 0..15  -> 16..23
    combine_mma_kernel<<<4, 256, SMEM_CMB>>>(16,  0, 0);  // 16..23 -> 0..3
    combine_mma_kernel<<<2, 256, SMEM_CMB>>>( 0, 16, 0);  // 0..3   -> 16..17
    combine_mma_kernel<<<1, 256, SMEM_CMB>>>(16,  0, 1);  // 16..17 -> g_R

    gemm_kernel<<<grid, 256, SMEM2>>>(X, mus, out);
}